// round 1
// baseline (speedup 1.0000x reference)
#include <cuda_runtime.h>

#define D 64

static const int NU = 30000, NB = 10000, NI = 60000;

// Static device scratch (allocation-free rule): max graph is UI with 90000 nodes.
__device__ float g_feat [(30000 + 60000) * 64];
__device__ float g_feat2[(30000 + 60000) * 64];
__device__ float g_ub_acc[(30000 + 10000) * 64];
__device__ float g_ui_acc[(30000 + 60000) * 64];
__device__ float g_bi_acc[(10000 + 60000) * 64];

// ---------------------------------------------------------------------------
// feat = concat(a, b); acc = coefs[0] * feat
__global__ void k_init(const float* __restrict__ a, const float* __restrict__ b,
                       int na_elems, int tot_elems,
                       const float* __restrict__ coefs,
                       float* __restrict__ feat, float* __restrict__ acc) {
    int i = blockIdx.x * blockDim.x + threadIdx.x;
    if (i >= tot_elems) return;
    float v = (i < na_elems) ? a[i] : b[i - na_elems];
    feat[i] = v;
    acc[i] = coefs[0] * v;
}

__global__ void k_zero(float* __restrict__ p, int n) {
    int i = blockIdx.x * blockDim.x + threadIdx.x;
    if (i < n) p[i] = 0.0f;
}

// Edge-parallel scatter SpMM: one warp per edge, lane handles cols d and d+32.
__global__ void k_spmm(const int* __restrict__ rows, const int* __restrict__ cols,
                       const float* __restrict__ vals, int nE,
                       const float* __restrict__ feat, float* __restrict__ out) {
    int w   = (blockIdx.x * blockDim.x + threadIdx.x) >> 5;
    int lid = threadIdx.x & 31;
    if (w >= nE) return;
    int   r = rows[w];
    int   c = cols[w];
    float v = vals[w];
    const float* src = feat + (size_t)c * D;
    float* dst = out + (size_t)r * D;
    atomicAdd(&dst[lid],      v * src[lid]);
    atomicAdd(&dst[lid + 32], v * src[lid + 32]);
}

// acc += coefs[li] * row / max(||row||, 1e-12) ; one warp per node row.
__global__ void k_norm_acc(const float* __restrict__ feat, float* __restrict__ acc,
                           int n_rows, const float* __restrict__ coefs, int li) {
    int w   = (blockIdx.x * blockDim.x + threadIdx.x) >> 5;
    int lid = threadIdx.x & 31;
    if (w >= n_rows) return;
    const float* src = feat + (size_t)w * D;
    float x0 = src[lid];
    float x1 = src[lid + 32];
    float s  = x0 * x0 + x1 * x1;
    #pragma unroll
    for (int o = 16; o; o >>= 1) s += __shfl_xor_sync(0xffffffffu, s, o);
    float inv = 1.0f / fmaxf(sqrtf(s), 1e-12f);
    float cc  = coefs[li];
    float* dst = acc + (size_t)w * D;
    dst[lid]      += cc * x0 * inv;
    dst[lid + 32] += cc * x1 * inv;
}

// out[user rows]   = m0*ub_acc_users   + m1*ui_acc_users
// out[bundle rows] = m0*ub_acc_bundles + m2*bi_acc_bundles
__global__ void k_combine(const float* __restrict__ ub_acc,
                          const float* __restrict__ ui_acc,
                          const float* __restrict__ bi_acc,
                          const float* __restrict__ modal,
                          float* __restrict__ out) {
    int i = blockIdx.x * blockDim.x + threadIdx.x;
    int nu_e = NU * D;
    int tot  = (NU + NB) * D;
    if (i >= tot) return;
    if (i < nu_e) {
        out[i] = modal[0] * ub_acc[i] + modal[1] * ui_acc[i];
    } else {
        int j = i - nu_e;
        out[i] = modal[0] * ub_acc[nu_e + j] + modal[2] * bi_acc[j];
    }
}

// Aggregation SpMM directly into d_out with modal scaling:
// out[(out_row_off + rows[e]) , :] += modal[midx] * vals[e] * feat[(feat_off + cols[e]), :]
__global__ void k_agg(const int* __restrict__ rows, const int* __restrict__ cols,
                      const float* __restrict__ vals, int nE,
                      const float* __restrict__ feat, int feat_node_off,
                      const float* __restrict__ modal, int midx,
                      float* __restrict__ out, int out_row_off) {
    int w   = (blockIdx.x * blockDim.x + threadIdx.x) >> 5;
    int lid = threadIdx.x & 31;
    if (w >= nE) return;
    float v = modal[midx] * vals[w];
    const float* src = feat + (size_t)(feat_node_off + cols[w]) * D;
    float* dst = out + (size_t)(out_row_off + rows[w]) * D;
    atomicAdd(&dst[lid],      v * src[lid]);
    atomicAdd(&dst[lid + 32], v * src[lid + 32]);
}

// ---------------------------------------------------------------------------
static inline int ceil_div(int a, int b) { return (a + b - 1) / b; }

static void run_propagate(const int* rows, const int* cols, const float* vals, int nE,
                          const float* a, const float* b, int na, int nb,
                          const float* coefs,
                          float* feat, float* feat2, float* acc) {
    const int TB = 256;
    int n_nodes = na + nb;
    int n_elems = n_nodes * D;

    k_init<<<ceil_div(n_elems, TB), TB>>>(a, b, na * D, n_elems, coefs, feat, acc);

    float* cur = feat;
    float* nxt = feat2;
    for (int layer = 0; layer < 2; layer++) {
        k_zero<<<ceil_div(n_elems, TB), TB>>>(nxt, n_elems);
        k_spmm<<<ceil_div(nE * 32, TB), TB>>>(rows, cols, vals, nE, cur, nxt);
        k_norm_acc<<<ceil_div(n_nodes * 32, TB), TB>>>(nxt, acc, n_nodes, coefs, layer + 1);
        float* t = cur; cur = nxt; nxt = t;
    }
}

extern "C" void kernel_launch(void* const* d_in, const int* in_sizes, int n_in,
                              void* d_out, int out_size) {
    const float* users   = (const float*)d_in[0];
    const float* bundles = (const float*)d_in[1];
    const float* items   = (const float*)d_in[2];
    const int*   ub_rows = (const int*)d_in[3];
    const int*   ub_cols = (const int*)d_in[4];
    const float* ub_vals = (const float*)d_in[5];
    const int*   ui_rows = (const int*)d_in[6];
    const int*   ui_cols = (const int*)d_in[7];
    const float* ui_vals = (const float*)d_in[8];
    const int*   bi_rows = (const int*)d_in[9];
    const int*   bi_cols = (const int*)d_in[10];
    const float* bi_vals = (const float*)d_in[11];
    const int*   bi_agg_rows = (const int*)d_in[12];
    const int*   bi_agg_cols = (const int*)d_in[13];
    const float* bi_agg_vals = (const float*)d_in[14];
    const int*   ui_agg_rows = (const int*)d_in[15];
    const int*   ui_agg_cols = (const int*)d_in[16];
    const float* ui_agg_vals = (const float*)d_in[17];
    const float* ub_coefs  = (const float*)d_in[18];
    const float* ui_coefs  = (const float*)d_in[19];
    const float* bi_coefs  = (const float*)d_in[20];
    const float* modal     = (const float*)d_in[21];

    int nE_ub = in_sizes[3];   // 2*E_UB
    int nE_ui = in_sizes[6];   // 2*E_UI
    int nE_bi = in_sizes[9];   // 2*E_BI
    int nE_bi_agg = in_sizes[12];
    int nE_ui_agg = in_sizes[15];

    float *feat, *feat2, *ub_acc, *ui_acc, *bi_acc;
    cudaGetSymbolAddress((void**)&feat,   g_feat);
    cudaGetSymbolAddress((void**)&feat2,  g_feat2);
    cudaGetSymbolAddress((void**)&ub_acc, g_ub_acc);
    cudaGetSymbolAddress((void**)&ui_acc, g_ui_acc);
    cudaGetSymbolAddress((void**)&bi_acc, g_bi_acc);

    float* out = (float*)d_out;
    const int TB = 256;

    // Three modal propagations (sequential; reuse feat ping-pong buffers).
    run_propagate(ub_rows, ub_cols, ub_vals, nE_ub, users,   bundles, NU, NB, ub_coefs, feat, feat2, ub_acc);
    run_propagate(ui_rows, ui_cols, ui_vals, nE_ui, users,   items,   NU, NI, ui_coefs, feat, feat2, ui_acc);
    run_propagate(bi_rows, bi_cols, bi_vals, nE_bi, bundles, items,   NB, NI, bi_coefs, feat, feat2, bi_acc);

    // Base combine into d_out (users rows then bundles rows).
    k_combine<<<ceil_div((NU + NB) * D, TB), TB>>>(ub_acc, ui_acc, bi_acc, modal, out);

    // bi_u into users rows: UI_agg @ (bi items part), scaled by modal[2].
    k_agg<<<ceil_div(nE_ui_agg * 32, TB), TB>>>(ui_agg_rows, ui_agg_cols, ui_agg_vals, nE_ui_agg,
                                               bi_acc, NB, modal, 2, out, 0);
    // ui_b into bundle rows: BI_agg @ (ui items part), scaled by modal[1].
    k_agg<<<ceil_div(nE_bi_agg * 32, TB), TB>>>(bi_agg_rows, bi_agg_cols, bi_agg_vals, nE_bi_agg,
                                               ui_acc, NU, modal, 1, out, NU);
}

// round 3
// speedup vs baseline: 1.7657x; 1.7657x over previous
#include <cuda_runtime.h>

#define D 64
#define D4 16   // D/4 float4s per row

static const int NU = 30000, NB = 10000, NI = 60000;

// Static device scratch (allocation-free rule): max graph is UI with 90000 nodes.
__device__ float g_feat [(30000 + 60000) * 64];
__device__ float g_feat2[(30000 + 60000) * 64];
__device__ float g_ub_acc[(30000 + 10000) * 64];
__device__ float g_ui_acc[(30000 + 60000) * 64];
__device__ float g_bi_acc[(10000 + 60000) * 64];

__device__ __forceinline__ void red_add_v4(float* addr, float4 v) {
    asm volatile("red.global.add.v4.f32 [%0], {%1, %2, %3, %4};"
                 :: "l"(addr), "f"(v.x), "f"(v.y), "f"(v.z), "f"(v.w)
                 : "memory");
}

// ---------------------------------------------------------------------------
// feat = concat(a, b); acc = coefs[0] * feat; zbuf = 0  (all float4 indexed)
__global__ void k_init(const float4* __restrict__ a, const float4* __restrict__ b,
                       int na_v4, int tot_v4,
                       const float* __restrict__ coefs,
                       float4* __restrict__ feat, float4* __restrict__ acc,
                       float4* __restrict__ zbuf) {
    int i = blockIdx.x * blockDim.x + threadIdx.x;
    if (i >= tot_v4) return;
    float4 v = (i < na_v4) ? a[i] : b[i - na_v4];
    float c = coefs[0];
    feat[i] = v;
    acc[i] = make_float4(c * v.x, c * v.y, c * v.z, c * v.w);
    zbuf[i] = make_float4(0.f, 0.f, 0.f, 0.f);
}

// Edge-parallel scatter SpMM: 2 edges per warp, 16 lanes per edge,
// each lane moves one float4 (LDG.128 gather + RED.128 scatter).
__global__ void k_spmm(const int* __restrict__ rows, const int* __restrict__ cols,
                       const float* __restrict__ vals, int nE,
                       const float* __restrict__ feat, float* __restrict__ out) {
    int w    = (blockIdx.x * blockDim.x + threadIdx.x) >> 5;
    int lid  = threadIdx.x & 31;
    int e    = 2 * w + (lid >> 4);     // edge handled by this half-warp
    int q    = lid & 15;               // float4 index within row
    if (e >= nE) return;
    int   r = rows[e];
    int   c = cols[e];
    float v = vals[e];
    const float4* src = (const float4*)(feat + (size_t)c * D);
    float*        dst = out + (size_t)r * D + q * 4;
    float4 s = src[q];
    red_add_v4(dst, make_float4(v * s.x, v * s.y, v * s.z, v * s.w));
}

// acc += coefs[li] * row / max(||row||, 1e-12); 2 rows per warp, float4.
// Also zeros zbuf rows (the next layer's scatter destination) when nonzero.
__global__ void k_norm_acc(const float* __restrict__ feat, float* __restrict__ acc,
                           int n_rows, const float* __restrict__ coefs, int li,
                           float* __restrict__ zbuf) {
    int w   = (blockIdx.x * blockDim.x + threadIdx.x) >> 5;
    int lid = threadIdx.x & 31;
    int row = 2 * w + (lid >> 4);
    int q   = lid & 15;
    if (row >= n_rows) return;
    const float4* src = (const float4*)(feat + (size_t)row * D);
    float4 x = src[q];
    float s = x.x * x.x + x.y * x.y + x.z * x.z + x.w * x.w;
    #pragma unroll
    for (int o = 8; o; o >>= 1) s += __shfl_xor_sync(0xffffffffu, s, o);
    float k = coefs[li] / fmaxf(sqrtf(s), 1e-12f);
    float4* dst = (float4*)(acc + (size_t)row * D);
    float4 av = dst[q];
    av.x += k * x.x; av.y += k * x.y; av.z += k * x.z; av.w += k * x.w;
    dst[q] = av;
    if (zbuf) {
        float4* z = (float4*)(zbuf + (size_t)row * D);
        z[q] = make_float4(0.f, 0.f, 0.f, 0.f);
    }
}

// out[user rows]   = m0*ub_acc_users   + m1*ui_acc_users
// out[bundle rows] = m0*ub_acc_bundles + m2*bi_acc_bundles   (float4 indexed)
__global__ void k_combine(const float4* __restrict__ ub_acc,
                          const float4* __restrict__ ui_acc,
                          const float4* __restrict__ bi_acc,
                          const float* __restrict__ modal,
                          float4* __restrict__ out) {
    int i = blockIdx.x * blockDim.x + threadIdx.x;
    int nu_v4 = NU * D4;
    int tot   = (NU + NB) * D4;
    if (i >= tot) return;
    float m0 = modal[0];
    float4 u = ub_acc[i];
    float4 o;
    if (i < nu_v4) {
        float m1 = modal[1];
        float4 t = ui_acc[i];
        o = make_float4(m0 * u.x + m1 * t.x, m0 * u.y + m1 * t.y,
                        m0 * u.z + m1 * t.z, m0 * u.w + m1 * t.w);
    } else {
        float m2 = modal[2];
        float4 t = bi_acc[i - nu_v4];
        o = make_float4(m0 * u.x + m2 * t.x, m0 * u.y + m2 * t.y,
                        m0 * u.z + m2 * t.z, m0 * u.w + m2 * t.w);
    }
    out[i] = o;
}

// Aggregation SpMM directly into d_out with modal scaling (2 edges/warp, float4).
__global__ void k_agg(const int* __restrict__ rows, const int* __restrict__ cols,
                      const float* __restrict__ vals, int nE,
                      const float* __restrict__ feat, int feat_node_off,
                      const float* __restrict__ modal, int midx,
                      float* __restrict__ out, int out_row_off) {
    int w   = (blockIdx.x * blockDim.x + threadIdx.x) >> 5;
    int lid = threadIdx.x & 31;
    int e   = 2 * w + (lid >> 4);
    int q   = lid & 15;
    if (e >= nE) return;
    float v = modal[midx] * vals[e];
    const float4* src = (const float4*)(feat + (size_t)(feat_node_off + cols[e]) * D);
    float*        dst = out + (size_t)(out_row_off + rows[e]) * D + q * 4;
    float4 s = src[q];
    red_add_v4(dst, make_float4(v * s.x, v * s.y, v * s.z, v * s.w));
}

// ---------------------------------------------------------------------------
static inline int ceil_div(int a, int b) { return (a + b - 1) / b; }

static void run_propagate(const int* rows, const int* cols, const float* vals, int nE,
                          const float* a, const float* b, int na, int nb,
                          const float* coefs,
                          float* feat, float* feat2, float* acc) {
    const int TB = 256;
    int n_nodes = na + nb;
    int n_v4 = n_nodes * D4;

    // init: feat = concat, acc = c0*feat, feat2 zeroed (layer-0 scatter target)
    k_init<<<ceil_div(n_v4, TB), TB>>>((const float4*)a, (const float4*)b,
                                       na * D4, n_v4, coefs,
                                       (float4*)feat, (float4*)acc, (float4*)feat2);

    int spmm_threads = ceil_div(nE, 2) * 32;

    // layer 0: feat -> feat2 ; norm_acc zeros feat (layer-1 scatter target)
    k_spmm<<<ceil_div(spmm_threads, TB), TB>>>(rows, cols, vals, nE, feat, feat2);
    k_norm_acc<<<ceil_div(n_nodes * 16, TB), TB>>>(feat2, acc, n_nodes, coefs, 1, feat);

    // layer 1: feat2 -> feat ; no further zeroing needed
    k_spmm<<<ceil_div(spmm_threads, TB), TB>>>(rows, cols, vals, nE, feat2, feat);
    k_norm_acc<<<ceil_div(n_nodes * 16, TB), TB>>>(feat, acc, n_nodes, coefs, 2, nullptr);
}

extern "C" void kernel_launch(void* const* d_in, const int* in_sizes, int n_in,
                              void* d_out, int out_size) {
    const float* users   = (const float*)d_in[0];
    const float* bundles = (const float*)d_in[1];
    const float* items   = (const float*)d_in[2];
    const int*   ub_rows = (const int*)d_in[3];
    const int*   ub_cols = (const int*)d_in[4];
    const float* ub_vals = (const float*)d_in[5];
    const int*   ui_rows = (const int*)d_in[6];
    const int*   ui_cols = (const int*)d_in[7];
    const float* ui_vals = (const float*)d_in[8];
    const int*   bi_rows = (const int*)d_in[9];
    const int*   bi_cols = (const int*)d_in[10];
    const float* bi_vals = (const float*)d_in[11];
    const int*   bi_agg_rows = (const int*)d_in[12];
    const int*   bi_agg_cols = (const int*)d_in[13];
    const float* bi_agg_vals = (const float*)d_in[14];
    const int*   ui_agg_rows = (const int*)d_in[15];
    const int*   ui_agg_cols = (const int*)d_in[16];
    const float* ui_agg_vals = (const float*)d_in[17];
    const float* ub_coefs  = (const float*)d_in[18];
    const float* ui_coefs  = (const float*)d_in[19];
    const float* bi_coefs  = (const float*)d_in[20];
    const float* modal     = (const float*)d_in[21];

    int nE_ub = in_sizes[3];
    int nE_ui = in_sizes[6];
    int nE_bi = in_sizes[9];
    int nE_bi_agg = in_sizes[12];
    int nE_ui_agg = in_sizes[15];

    float *feat, *feat2, *ub_acc, *ui_acc, *bi_acc;
    cudaGetSymbolAddress((void**)&feat,   g_feat);
    cudaGetSymbolAddress((void**)&feat2,  g_feat2);
    cudaGetSymbolAddress((void**)&ub_acc, g_ub_acc);
    cudaGetSymbolAddress((void**)&ui_acc, g_ui_acc);
    cudaGetSymbolAddress((void**)&bi_acc, g_bi_acc);

    float* out = (float*)d_out;
    const int TB = 256;

    run_propagate(ub_rows, ub_cols, ub_vals, nE_ub, users,   bundles, NU, NB, ub_coefs, feat, feat2, ub_acc);
    run_propagate(ui_rows, ui_cols, ui_vals, nE_ui, users,   items,   NU, NI, ui_coefs, feat, feat2, ui_acc);
    run_propagate(bi_rows, bi_cols, bi_vals, nE_bi, bundles, items,   NB, NI, bi_coefs, feat, feat2, bi_acc);

    // Base combine into d_out (users rows then bundles rows).
    k_combine<<<ceil_div((NU + NB) * D4, TB), TB>>>((const float4*)ub_acc, (const float4*)ui_acc,
                                                    (const float4*)bi_acc, modal, (float4*)out);

    // bi_u into users rows: UI_agg @ (bi items part), scaled by modal[2].
    k_agg<<<ceil_div(ceil_div(nE_ui_agg, 2) * 32, TB), TB>>>(ui_agg_rows, ui_agg_cols, ui_agg_vals, nE_ui_agg,
                                                             bi_acc, NB, modal, 2, out, 0);
    // ui_b into bundle rows: BI_agg @ (ui items part), scaled by modal[1].
    k_agg<<<ceil_div(ceil_div(nE_bi_agg, 2) * 32, TB), TB>>>(bi_agg_rows, bi_agg_cols, bi_agg_vals, nE_bi_agg,
                                                             ui_acc, NU, modal, 1, out, NU);
}

// round 4
// speedup vs baseline: 2.3481x; 1.3298x over previous
#include <cuda_runtime.h>

#define D 64
#define D4 16   // float4s per row

static const int NU = 30000, NB = 10000, NI = 60000;
#define MAX_NODES 90001
#define MAX_EDGES 1600000
#define SCAN_TB 256

// Static device scratch (allocation-free rule).
__device__ float g_feat [90000 * 64];
__device__ float g_feat2[90000 * 64];
__device__ float g_ub_acc[40000 * 64];
__device__ float g_ui_acc[90000 * 64];
__device__ float g_bi_acc[70000 * 64];
__device__ int   g_cnt[MAX_NODES];
__device__ int   g_rowptr[MAX_NODES + 1];
__device__ int2  g_colval[MAX_EDGES];
__device__ int   g_partials[512];

// ---------------------------------------------------------------------------
// CSR build: histogram -> 3-pass exclusive scan -> atomic scatter
__global__ void k_zero_int(int* __restrict__ p, int n) {
    int i = blockIdx.x * blockDim.x + threadIdx.x;
    if (i < n) p[i] = 0;
}

__global__ void k_hist(const int* __restrict__ rows, int nE, int* __restrict__ cnt) {
    int i = blockIdx.x * blockDim.x + threadIdx.x;
    if (i < nE) atomicAdd(&cnt[rows[i]], 1);
}

__global__ void k_partial(const int* __restrict__ cnt, int n, int* __restrict__ partials) {
    __shared__ int s[SCAN_TB];
    int i = blockIdx.x * SCAN_TB + threadIdx.x;
    int t = threadIdx.x;
    s[t] = (i < n) ? cnt[i] : 0;
    __syncthreads();
    for (int o = SCAN_TB / 2; o; o >>= 1) {
        if (t < o) s[t] += s[t + o];
        __syncthreads();
    }
    if (t == 0) partials[blockIdx.x] = s[0];
}

__global__ void k_scan_partials(int* __restrict__ p, int nblk) {
    __shared__ int s[512];
    int t = threadIdx.x;
    s[t] = (t < nblk) ? p[t] : 0;
    __syncthreads();
    for (int o = 1; o < 512; o <<= 1) {
        int v = (t >= o) ? s[t - o] : 0;
        __syncthreads();
        s[t] += v;
        __syncthreads();
    }
    if (t < nblk) p[t] = (t ? s[t - 1] : 0);
}

__global__ void k_scan_final(int* __restrict__ cnt, int n,
                             const int* __restrict__ partials, int* __restrict__ rowptr) {
    __shared__ int s[SCAN_TB];
    int i = blockIdx.x * SCAN_TB + threadIdx.x;
    int t = threadIdx.x;
    int c = (i < n) ? cnt[i] : 0;
    s[t] = c;
    __syncthreads();
    for (int o = 1; o < SCAN_TB; o <<= 1) {
        int v = (t >= o) ? s[t - o] : 0;
        __syncthreads();
        s[t] += v;
        __syncthreads();
    }
    int start = partials[blockIdx.x] + s[t] - c;   // exclusive
    if (i < n) {
        rowptr[i] = start;
        cnt[i] = start;                             // write positions for scatter
        if (i == n - 1) rowptr[n] = start + c;
    }
}

__global__ void k_scatter(const int* __restrict__ rows, const int* __restrict__ cols,
                          const float* __restrict__ vals, int nE,
                          int* __restrict__ pos, int2* __restrict__ colval) {
    int i = blockIdx.x * blockDim.x + threadIdx.x;
    if (i >= nE) return;
    int p = atomicAdd(&pos[rows[i]], 1);
    colval[p] = make_int2(cols[i], __float_as_int(vals[i]));
}

// ---------------------------------------------------------------------------
// feat = concat(a, b); acc = coefs[0] * feat
__global__ void k_init(const float4* __restrict__ a, const float4* __restrict__ b,
                       int na_v4, int tot_v4,
                       const float* __restrict__ coefs,
                       float4* __restrict__ feat, float4* __restrict__ acc) {
    int i = blockIdx.x * blockDim.x + threadIdx.x;
    if (i >= tot_v4) return;
    float4 v = (i < na_v4) ? a[i] : b[i - na_v4];
    float c = coefs[0];
    feat[i] = v;
    acc[i] = make_float4(c * v.x, c * v.y, c * v.z, c * v.w);
}

// Row-parallel CSR SpMM fused with l2norm accumulation.
// One warp per output row: 2 half-warps each process alternate edges;
// lane q in each half accumulates float4 column q. Writes raw row to feat_out
// and acc_buf += coefs[li] * row / max(||row||, 1e-12).
__global__ void k_spmm_csr(const int* __restrict__ rowptr, const int2* __restrict__ colval,
                           const float4* __restrict__ feat, int n_rows,
                           float4* __restrict__ feat_out, float4* __restrict__ acc_buf,
                           const float* __restrict__ coefs, int li) {
    int w   = (blockIdx.x * blockDim.x + threadIdx.x) >> 5;
    int lid = threadIdx.x & 31;
    if (w >= n_rows) return;
    int half = lid >> 4, q = lid & 15;
    int s = rowptr[w], e = rowptr[w + 1];
    float4 acc = make_float4(0.f, 0.f, 0.f, 0.f);
    #pragma unroll 2
    for (int j = s + half; j < e; j += 2) {
        int2 cv = colval[j];
        float v = __int_as_float(cv.y);
        float4 x = feat[cv.x * D4 + q];
        acc.x += v * x.x; acc.y += v * x.y; acc.z += v * x.z; acc.w += v * x.w;
    }
    acc.x += __shfl_xor_sync(0xffffffffu, acc.x, 16);
    acc.y += __shfl_xor_sync(0xffffffffu, acc.y, 16);
    acc.z += __shfl_xor_sync(0xffffffffu, acc.z, 16);
    acc.w += __shfl_xor_sync(0xffffffffu, acc.w, 16);
    float ss = acc.x * acc.x + acc.y * acc.y + acc.z * acc.z + acc.w * acc.w;
    #pragma unroll
    for (int o = 8; o; o >>= 1) ss += __shfl_xor_sync(0xffffffffu, ss, o);
    float k = coefs[li] / fmaxf(sqrtf(ss), 1e-12f);
    if (half == 0) {
        int idx = w * D4 + q;
        feat_out[idx] = acc;
        float4 a = acc_buf[idx];
        a.x += k * acc.x; a.y += k * acc.y; a.z += k * acc.z; a.w += k * acc.w;
        acc_buf[idx] = a;
    }
}

// out[user row] = m0*ub_acc + m1*ui_acc + m2 * sum_edges(v * bi_acc_items[col])
__global__ void k_out_users(const int* __restrict__ rowptr, const int2* __restrict__ colval,
                            const float4* __restrict__ bi_acc,
                            const float4* __restrict__ ub_acc,
                            const float4* __restrict__ ui_acc,
                            const float* __restrict__ modal, float4* __restrict__ out) {
    int w   = (blockIdx.x * blockDim.x + threadIdx.x) >> 5;
    int lid = threadIdx.x & 31;
    if (w >= NU) return;
    int half = lid >> 4, q = lid & 15;
    int s = rowptr[w], e = rowptr[w + 1];
    float4 agg = make_float4(0.f, 0.f, 0.f, 0.f);
    #pragma unroll 2
    for (int j = s + half; j < e; j += 2) {
        int2 cv = colval[j];
        float v = __int_as_float(cv.y);
        float4 x = bi_acc[(NB + cv.x) * D4 + q];
        agg.x += v * x.x; agg.y += v * x.y; agg.z += v * x.z; agg.w += v * x.w;
    }
    agg.x += __shfl_xor_sync(0xffffffffu, agg.x, 16);
    agg.y += __shfl_xor_sync(0xffffffffu, agg.y, 16);
    agg.z += __shfl_xor_sync(0xffffffffu, agg.z, 16);
    agg.w += __shfl_xor_sync(0xffffffffu, agg.w, 16);
    if (half == 0) {
        float m0 = modal[0], m1 = modal[1], m2 = modal[2];
        int idx = w * D4 + q;
        float4 u = ub_acc[idx];
        float4 t = ui_acc[idx];
        out[idx] = make_float4(m0 * u.x + m1 * t.x + m2 * agg.x,
                               m0 * u.y + m1 * t.y + m2 * agg.y,
                               m0 * u.z + m1 * t.z + m2 * agg.z,
                               m0 * u.w + m1 * t.w + m2 * agg.w);
    }
}

// out[NU+row] = m0*ub_acc_bundles + m2*bi_acc_bundles + m1 * sum(v * ui_acc_items[col])
__global__ void k_out_bundles(const int* __restrict__ rowptr, const int2* __restrict__ colval,
                              const float4* __restrict__ ui_acc,
                              const float4* __restrict__ ub_acc,
                              const float4* __restrict__ bi_acc,
                              const float* __restrict__ modal, float4* __restrict__ out) {
    int w   = (blockIdx.x * blockDim.x + threadIdx.x) >> 5;
    int lid = threadIdx.x & 31;
    if (w >= NB) return;
    int half = lid >> 4, q = lid & 15;
    int s = rowptr[w], e = rowptr[w + 1];
    float4 agg = make_float4(0.f, 0.f, 0.f, 0.f);
    #pragma unroll 2
    for (int j = s + half; j < e; j += 2) {
        int2 cv = colval[j];
        float v = __int_as_float(cv.y);
        float4 x = ui_acc[(NU + cv.x) * D4 + q];
        agg.x += v * x.x; agg.y += v * x.y; agg.z += v * x.z; agg.w += v * x.w;
    }
    agg.x += __shfl_xor_sync(0xffffffffu, agg.x, 16);
    agg.y += __shfl_xor_sync(0xffffffffu, agg.y, 16);
    agg.z += __shfl_xor_sync(0xffffffffu, agg.z, 16);
    agg.w += __shfl_xor_sync(0xffffffffu, agg.w, 16);
    if (half == 0) {
        float m0 = modal[0], m1 = modal[1], m2 = modal[2];
        float4 u = ub_acc[(NU + w) * D4 + q];
        float4 t = bi_acc[w * D4 + q];
        out[(NU + w) * D4 + q] =
            make_float4(m0 * u.x + m2 * t.x + m1 * agg.x,
                        m0 * u.y + m2 * t.y + m1 * agg.y,
                        m0 * u.z + m2 * t.z + m1 * agg.z,
                        m0 * u.w + m2 * t.w + m1 * agg.w);
    }
}

// ---------------------------------------------------------------------------
static inline int ceil_div(int a, int b) { return (a + b - 1) / b; }

static void build_csr(const int* rows, const int* cols, const float* vals, int nE, int n,
                      int* cnt, int* rowptr, int2* colval, int* partials) {
    const int TB = 256;
    int nblk = ceil_div(n, SCAN_TB);
    k_zero_int<<<ceil_div(n, TB), TB>>>(cnt, n);
    k_hist<<<ceil_div(nE, TB), TB>>>(rows, nE, cnt);
    k_partial<<<nblk, SCAN_TB>>>(cnt, n, partials);
    k_scan_partials<<<1, 512>>>(partials, nblk);
    k_scan_final<<<nblk, SCAN_TB>>>(cnt, n, partials, rowptr);
    k_scatter<<<ceil_div(nE, TB), TB>>>(rows, cols, vals, nE, cnt, colval);
}

extern "C" void kernel_launch(void* const* d_in, const int* in_sizes, int n_in,
                              void* d_out, int out_size) {
    const float* users   = (const float*)d_in[0];
    const float* bundles = (const float*)d_in[1];
    const float* items   = (const float*)d_in[2];
    const int*   ub_rows = (const int*)d_in[3];
    const int*   ub_cols = (const int*)d_in[4];
    const float* ub_vals = (const float*)d_in[5];
    const int*   ui_rows = (const int*)d_in[6];
    const int*   ui_cols = (const int*)d_in[7];
    const float* ui_vals = (const float*)d_in[8];
    const int*   bi_rows = (const int*)d_in[9];
    const int*   bi_cols = (const int*)d_in[10];
    const float* bi_vals = (const float*)d_in[11];
    const int*   bi_agg_rows = (const int*)d_in[12];
    const int*   bi_agg_cols = (const int*)d_in[13];
    const float* bi_agg_vals = (const float*)d_in[14];
    const int*   ui_agg_rows = (const int*)d_in[15];
    const int*   ui_agg_cols = (const int*)d_in[16];
    const float* ui_agg_vals = (const float*)d_in[17];
    const float* ub_coefs  = (const float*)d_in[18];
    const float* ui_coefs  = (const float*)d_in[19];
    const float* bi_coefs  = (const float*)d_in[20];
    const float* modal     = (const float*)d_in[21];

    int nE_ub = in_sizes[3];
    int nE_ui = in_sizes[6];
    int nE_bi = in_sizes[9];
    int nE_bi_agg = in_sizes[12];
    int nE_ui_agg = in_sizes[15];

    float *feat, *feat2, *ub_acc, *ui_acc, *bi_acc;
    int *cnt, *rowptr, *partials;
    int2* colval;
    cudaGetSymbolAddress((void**)&feat,     g_feat);
    cudaGetSymbolAddress((void**)&feat2,    g_feat2);
    cudaGetSymbolAddress((void**)&ub_acc,   g_ub_acc);
    cudaGetSymbolAddress((void**)&ui_acc,   g_ui_acc);
    cudaGetSymbolAddress((void**)&bi_acc,   g_bi_acc);
    cudaGetSymbolAddress((void**)&cnt,      g_cnt);
    cudaGetSymbolAddress((void**)&rowptr,   g_rowptr);
    cudaGetSymbolAddress((void**)&colval,   g_colval);
    cudaGetSymbolAddress((void**)&partials, g_partials);

    float* out = (float*)d_out;
    const int TB = 256;

    struct Prop {
        const int *rows, *cols; const float *vals; int nE;
        const float *a, *b; int na, nb;
        const float* coefs; float* acc;
    } props[3] = {
        { ub_rows, ub_cols, ub_vals, nE_ub, users,   bundles, NU, NB, ub_coefs, ub_acc },
        { ui_rows, ui_cols, ui_vals, nE_ui, users,   items,   NU, NI, ui_coefs, ui_acc },
        { bi_rows, bi_cols, bi_vals, nE_bi, bundles, items,   NB, NI, bi_coefs, bi_acc },
    };

    for (int g = 0; g < 3; g++) {
        Prop& p = props[g];
        int n_nodes = p.na + p.nb;
        int n_v4 = n_nodes * D4;
        build_csr(p.rows, p.cols, p.vals, p.nE, n_nodes, cnt, rowptr, colval, partials);
        k_init<<<ceil_div(n_v4, TB), TB>>>((const float4*)p.a, (const float4*)p.b,
                                           p.na * D4, n_v4, p.coefs,
                                           (float4*)feat, (float4*)p.acc);
        int spmm_blocks = ceil_div(n_nodes * 32, TB);
        k_spmm_csr<<<spmm_blocks, TB>>>(rowptr, colval, (const float4*)feat, n_nodes,
                                        (float4*)feat2, (float4*)p.acc, p.coefs, 1);
        k_spmm_csr<<<spmm_blocks, TB>>>(rowptr, colval, (const float4*)feat2, n_nodes,
                                        (float4*)feat, (float4*)p.acc, p.coefs, 2);
    }

    // users output rows: ui_agg graph (rows in [0,NU)), gather from bi items.
    build_csr(ui_agg_rows, ui_agg_cols, ui_agg_vals, nE_ui_agg, NU, cnt, rowptr, colval, partials);
    k_out_users<<<ceil_div(NU * 32, TB), TB>>>(rowptr, colval, (const float4*)bi_acc,
                                               (const float4*)ub_acc, (const float4*)ui_acc,
                                               modal, (float4*)out);

    // bundle output rows: bi_agg graph (rows in [0,NB)), gather from ui items.
    build_csr(bi_agg_rows, bi_agg_cols, bi_agg_vals, nE_bi_agg, NB, cnt, rowptr, colval, partials);
    k_out_bundles<<<ceil_div(NB * 32, TB), TB>>>(rowptr, colval, (const float4*)ui_acc,
                                                 (const float4*)ub_acc, (const float4*)bi_acc,
                                                 modal, (float4*)out);
}

// round 6
// speedup vs baseline: 2.5152x; 1.0712x over previous
#include <cuda_runtime.h>

#define D 64
#define D4 16   // float4s per row

static const int NU = 30000, NB = 10000, NI = 60000;

// Concatenated node space: UB(40000) | UI(90000) | BI(70000) | UIagg(30000) | BIagg(10000)
#define TOT_NODES 240000
// Concatenated edge space: 800k | 1.6M | 1.6M | 800k | 800k
#define TOT_EDGES 5600000
#define SCAN_TB 512
#define MAX_BLKS 512   // ceil(240000/512)=469 <= 512

// Static device scratch (allocation-free rule).
__device__ float g_feat  [90000 * 64];
__device__ float g_feat2 [90000 * 64];
__device__ float g_ub_acc[40000 * 64];
__device__ float g_ui_acc[90000 * 64];
__device__ float g_bi_acc[70000 * 64];
__device__ int   g_cnt   [TOT_NODES];
__device__ int   g_rowptr[TOT_NODES + 1];
__device__ int2  g_colval[TOT_EDGES];
__device__ int   g_partials[MAX_BLKS];

struct GraphSet {
    const int*   rows[5];
    const int*   cols[5];
    const float* vals[5];
    int e_base[6];   // cumulative edge offsets
    int n_base[6];   // cumulative node offsets
};

// ---------------------------------------------------------------------------
__global__ void k_zero_int(int* __restrict__ p, int n) {
    int i = blockIdx.x * blockDim.x + threadIdx.x;
    if (i < n) p[i] = 0;
}

// Fused histogram over all 5 graphs (concatenated edge index).
__global__ void k_hist_all(GraphSet gs, int tot_e, int* __restrict__ cnt) {
    int i = blockIdx.x * blockDim.x + threadIdx.x;
    if (i >= tot_e) return;
    int g = 0;
    #pragma unroll
    for (int k = 1; k < 5; k++) if (i >= gs.e_base[k]) g = k;
    int ei = i - gs.e_base[g];
    atomicAdd(&cnt[gs.n_base[g] + gs.rows[g][ei]], 1);
}

__global__ void k_partial(const int* __restrict__ cnt, int n, int* __restrict__ partials) {
    __shared__ int s[SCAN_TB];
    int i = blockIdx.x * SCAN_TB + threadIdx.x;
    int t = threadIdx.x;
    s[t] = (i < n) ? cnt[i] : 0;
    __syncthreads();
    for (int o = SCAN_TB / 2; o; o >>= 1) {
        if (t < o) s[t] += s[t + o];
        __syncthreads();
    }
    if (t == 0) partials[blockIdx.x] = s[0];
}

__global__ void k_scan_partials(int* __restrict__ p, int nblk) {
    __shared__ int s[MAX_BLKS];
    int t = threadIdx.x;
    s[t] = (t < nblk) ? p[t] : 0;
    __syncthreads();
    for (int o = 1; o < MAX_BLKS; o <<= 1) {
        int v = (t >= o) ? s[t - o] : 0;
        __syncthreads();
        s[t] += v;
        __syncthreads();
    }
    if (t < nblk) p[t] = (t ? s[t - 1] : 0);
}

__global__ void k_scan_final(int* __restrict__ cnt, int n,
                             const int* __restrict__ partials, int* __restrict__ rowptr) {
    __shared__ int s[SCAN_TB];
    int i = blockIdx.x * SCAN_TB + threadIdx.x;
    int t = threadIdx.x;
    int c = (i < n) ? cnt[i] : 0;
    s[t] = c;
    __syncthreads();
    for (int o = 1; o < SCAN_TB; o <<= 1) {
        int v = (t >= o) ? s[t - o] : 0;
        __syncthreads();
        s[t] += v;
        __syncthreads();
    }
    int start = partials[blockIdx.x] + s[t] - c;   // exclusive
    if (i < n) {
        rowptr[i] = start;
        cnt[i] = start;                             // scatter write positions
        if (i == n - 1) rowptr[n] = start + c;
    }
}

// Fused scatter over all 5 graphs into the global colval array.
__global__ void k_scatter_all(GraphSet gs, int tot_e,
                              int* __restrict__ pos, int2* __restrict__ colval) {
    int i = blockIdx.x * blockDim.x + threadIdx.x;
    if (i >= tot_e) return;
    int g = 0;
    #pragma unroll
    for (int k = 1; k < 5; k++) if (i >= gs.e_base[k]) g = k;
    int ei = i - gs.e_base[g];
    int p = atomicAdd(&pos[gs.n_base[g] + gs.rows[g][ei]], 1);
    colval[p] = make_int2(gs.cols[g][ei], __float_as_int(gs.vals[g][ei]));
}

// ---------------------------------------------------------------------------
// feat = concat(a, b); acc = coefs[0] * feat
__global__ void k_init(const float4* __restrict__ a, const float4* __restrict__ b,
                       int na_v4, int tot_v4,
                       const float* __restrict__ coefs,
                       float4* __restrict__ feat, float4* __restrict__ acc) {
    int i = blockIdx.x * blockDim.x + threadIdx.x;
    if (i >= tot_v4) return;
    float4 v = (i < na_v4) ? a[i] : b[i - na_v4];
    float c = coefs[0];
    feat[i] = v;
    acc[i] = make_float4(c * v.x, c * v.y, c * v.z, c * v.w);
}

__device__ __forceinline__ void fma4(float4& a, float v, float4 x) {
    a.x += v * x.x; a.y += v * x.y; a.z += v * x.z; a.w += v * x.w;
}

// Row-parallel CSR SpMM fused with l2norm accumulation. One warp per row,
// halves take alternating edges, unroll x4 for gather MLP.
__global__ void k_spmm_csr(const int* __restrict__ rowptr, const int2* __restrict__ colval,
                           const float4* __restrict__ feat, int n_rows,
                           float4* __restrict__ feat_out, float4* __restrict__ acc_buf,
                           const float* __restrict__ coefs, int li) {
    int w   = (blockIdx.x * blockDim.x + threadIdx.x) >> 5;
    int lid = threadIdx.x & 31;
    if (w >= n_rows) return;
    int half = lid >> 4, q = lid & 15;
    int s = rowptr[w], e = rowptr[w + 1];
    float4 a0 = make_float4(0.f, 0.f, 0.f, 0.f);
    float4 a1 = make_float4(0.f, 0.f, 0.f, 0.f);
    int j = s + half;
    for (; j + 6 < e; j += 8) {
        int2 c0 = colval[j], c1 = colval[j + 2], c2 = colval[j + 4], c3 = colval[j + 6];
        float4 x0 = feat[c0.x * D4 + q];
        float4 x1 = feat[c1.x * D4 + q];
        float4 x2 = feat[c2.x * D4 + q];
        float4 x3 = feat[c3.x * D4 + q];
        fma4(a0, __int_as_float(c0.y), x0);
        fma4(a1, __int_as_float(c1.y), x1);
        fma4(a0, __int_as_float(c2.y), x2);
        fma4(a1, __int_as_float(c3.y), x3);
    }
    for (; j < e; j += 2) {
        int2 cv = colval[j];
        fma4(a0, __int_as_float(cv.y), feat[cv.x * D4 + q]);
    }
    float4 acc = make_float4(a0.x + a1.x, a0.y + a1.y, a0.z + a1.z, a0.w + a1.w);
    acc.x += __shfl_xor_sync(0xffffffffu, acc.x, 16);
    acc.y += __shfl_xor_sync(0xffffffffu, acc.y, 16);
    acc.z += __shfl_xor_sync(0xffffffffu, acc.z, 16);
    acc.w += __shfl_xor_sync(0xffffffffu, acc.w, 16);
    float ss = acc.x * acc.x + acc.y * acc.y + acc.z * acc.z + acc.w * acc.w;
    #pragma unroll
    for (int o = 8; o; o >>= 1) ss += __shfl_xor_sync(0xffffffffu, ss, o);
    float k = coefs[li] / fmaxf(sqrtf(ss), 1e-12f);
    if (half == 0) {
        int idx = w * D4 + q;
        feat_out[idx] = acc;
        float4 a = acc_buf[idx];
        a.x += k * acc.x; a.y += k * acc.y; a.z += k * acc.z; a.w += k * acc.w;
        acc_buf[idx] = a;
    }
}

// out[row] = mA*accA[rowA] + mB*accB[rowB] + mC * sum_edges(v * gsrc[src_off+col])
__global__ void k_out(const int* __restrict__ rowptr, const int2* __restrict__ colval,
                      int n_rows,
                      const float4* __restrict__ gsrc, int src_off,
                      const float4* __restrict__ accA, int offA, float mA_idx_dummy,
                      const float4* __restrict__ accB, int offB,
                      const float* __restrict__ modal, int iA, int iB, int iC,
                      float4* __restrict__ out, int out_off) {
    int w   = (blockIdx.x * blockDim.x + threadIdx.x) >> 5;
    int lid = threadIdx.x & 31;
    if (w >= n_rows) return;
    int half = lid >> 4, q = lid & 15;
    int s = rowptr[w], e = rowptr[w + 1];
    float4 a0 = make_float4(0.f, 0.f, 0.f, 0.f);
    float4 a1 = make_float4(0.f, 0.f, 0.f, 0.f);
    int j = s + half;
    for (; j + 6 < e; j += 8) {
        int2 c0 = colval[j], c1 = colval[j + 2], c2 = colval[j + 4], c3 = colval[j + 6];
        float4 x0 = gsrc[(src_off + c0.x) * D4 + q];
        float4 x1 = gsrc[(src_off + c1.x) * D4 + q];
        float4 x2 = gsrc[(src_off + c2.x) * D4 + q];
        float4 x3 = gsrc[(src_off + c3.x) * D4 + q];
        fma4(a0, __int_as_float(c0.y), x0);
        fma4(a1, __int_as_float(c1.y), x1);
        fma4(a0, __int_as_float(c2.y), x2);
        fma4(a1, __int_as_float(c3.y), x3);
    }
    for (; j < e; j += 2) {
        int2 cv = colval[j];
        fma4(a0, __int_as_float(cv.y), gsrc[(src_off + cv.x) * D4 + q]);
    }
    float4 agg = make_float4(a0.x + a1.x, a0.y + a1.y, a0.z + a1.z, a0.w + a1.w);
    agg.x += __shfl_xor_sync(0xffffffffu, agg.x, 16);
    agg.y += __shfl_xor_sync(0xffffffffu, agg.y, 16);
    agg.z += __shfl_xor_sync(0xffffffffu, agg.z, 16);
    agg.w += __shfl_xor_sync(0xffffffffu, agg.w, 16);
    if (half == 0) {
        float mA = modal[iA], mB = modal[iB], mC = modal[iC];
        float4 u = accA[(offA + w) * D4 + q];
        float4 t = accB[(offB + w) * D4 + q];
        out[(out_off + w) * D4 + q] =
            make_float4(mA * u.x + mB * t.x + mC * agg.x,
                        mA * u.y + mB * t.y + mC * agg.y,
                        mA * u.z + mB * t.z + mC * agg.z,
                        mA * u.w + mB * t.w + mC * agg.w);
    }
}

// ---------------------------------------------------------------------------
static inline int ceil_div(int a, int b) { return (a + b - 1) / b; }

extern "C" void kernel_launch(void* const* d_in, const int* in_sizes, int n_in,
                              void* d_out, int out_size) {
    const float* users   = (const float*)d_in[0];
    const float* bundles = (const float*)d_in[1];
    const float* items   = (const float*)d_in[2];
    const int*   ub_rows = (const int*)d_in[3];
    const int*   ub_cols = (const int*)d_in[4];
    const float* ub_vals = (const float*)d_in[5];
    const int*   ui_rows = (const int*)d_in[6];
    const int*   ui_cols = (const int*)d_in[7];
    const float* ui_vals = (const float*)d_in[8];
    const int*   bi_rows = (const int*)d_in[9];
    const int*   bi_cols = (const int*)d_in[10];
    const float* bi_vals = (const float*)d_in[11];
    const int*   bi_agg_rows = (const int*)d_in[12];
    const int*   bi_agg_cols = (const int*)d_in[13];
    const float* bi_agg_vals = (const float*)d_in[14];
    const int*   ui_agg_rows = (const int*)d_in[15];
    const int*   ui_agg_cols = (const int*)d_in[16];
    const float* ui_agg_vals = (const float*)d_in[17];
    const float* ub_coefs  = (const float*)d_in[18];
    const float* ui_coefs  = (const float*)d_in[19];
    const float* bi_coefs  = (const float*)d_in[20];
    const float* modal     = (const float*)d_in[21];

    int nE_ub = in_sizes[3];
    int nE_ui = in_sizes[6];
    int nE_bi = in_sizes[9];
    int nE_bi_agg = in_sizes[12];
    int nE_ui_agg = in_sizes[15];

    float *feat, *feat2, *ub_acc, *ui_acc, *bi_acc;
    int *cnt, *rowptr, *partials;
    int2* colval;
    cudaGetSymbolAddress((void**)&feat,     g_feat);
    cudaGetSymbolAddress((void**)&feat2,    g_feat2);
    cudaGetSymbolAddress((void**)&ub_acc,   g_ub_acc);
    cudaGetSymbolAddress((void**)&ui_acc,   g_ui_acc);
    cudaGetSymbolAddress((void**)&bi_acc,   g_bi_acc);
    cudaGetSymbolAddress((void**)&cnt,      g_cnt);
    cudaGetSymbolAddress((void**)&rowptr,   g_rowptr);
    cudaGetSymbolAddress((void**)&colval,   g_colval);
    cudaGetSymbolAddress((void**)&partials, g_partials);

    float* out = (float*)d_out;
    const int TB = 256;

    // Graph order: 0=UB prop, 1=UI prop, 2=BI prop, 3=UI_agg(rows=users), 4=BI_agg(rows=bundles)
    GraphSet gs;
    gs.rows[0] = ub_rows;     gs.cols[0] = ub_cols;     gs.vals[0] = ub_vals;
    gs.rows[1] = ui_rows;     gs.cols[1] = ui_cols;     gs.vals[1] = ui_vals;
    gs.rows[2] = bi_rows;     gs.cols[2] = bi_cols;     gs.vals[2] = bi_vals;
    gs.rows[3] = ui_agg_rows; gs.cols[3] = ui_agg_cols; gs.vals[3] = ui_agg_vals;
    gs.rows[4] = bi_agg_rows; gs.cols[4] = bi_agg_cols; gs.vals[4] = bi_agg_vals;
    int nE[5] = { nE_ub, nE_ui, nE_bi, nE_ui_agg, nE_bi_agg };
    int nN[5] = { NU + NB, NU + NI, NB + NI, NU, NB };
    gs.e_base[0] = 0; gs.n_base[0] = 0;
    for (int g = 0; g < 5; g++) {
        gs.e_base[g + 1] = gs.e_base[g] + nE[g];
        gs.n_base[g + 1] = gs.n_base[g] + nN[g];
    }
    int tot_e = gs.e_base[5];
    int tot_n = gs.n_base[5];
    int nblk = ceil_div(tot_n, SCAN_TB);

    // ---- single batched CSR build for all 5 graphs (6 launches total) ----
    k_zero_int<<<ceil_div(tot_n, TB), TB>>>(cnt, tot_n);
    k_hist_all<<<ceil_div(tot_e, TB), TB>>>(gs, tot_e, cnt);
    k_partial<<<nblk, SCAN_TB>>>(cnt, tot_n, partials);
    k_scan_partials<<<1, MAX_BLKS>>>(partials, nblk);
    k_scan_final<<<nblk, SCAN_TB>>>(cnt, tot_n, partials, rowptr);
    k_scatter_all<<<ceil_div(tot_e, TB), TB>>>(gs, tot_e, cnt, colval);

    // ---- three propagations ----
    struct Prop {
        const float *a, *b; int na, nb;
        const float* coefs; float* acc; int gidx;
    } props[3] = {
        { users,   bundles, NU, NB, ub_coefs, ub_acc, 0 },
        { users,   items,   NU, NI, ui_coefs, ui_acc, 1 },
        { bundles, items,   NB, NI, bi_coefs, bi_acc, 2 },
    };
    for (int g = 0; g < 3; g++) {
        Prop& p = props[g];
        int n_nodes = p.na + p.nb;
        int n_v4 = n_nodes * D4;
        const int* rp = rowptr + gs.n_base[p.gidx];
        k_init<<<ceil_div(n_v4, TB), TB>>>((const float4*)p.a, (const float4*)p.b,
                                           p.na * D4, n_v4, p.coefs,
                                           (float4*)feat, (float4*)p.acc);
        int blocks = ceil_div(n_nodes * 32, TB);
        k_spmm_csr<<<blocks, TB>>>(rp, colval, (const float4*)feat, n_nodes,
                                   (float4*)feat2, (float4*)p.acc, p.coefs, 1);
        k_spmm_csr<<<blocks, TB>>>(rp, colval, (const float4*)feat2, n_nodes,
                                   (float4*)feat, (float4*)p.acc, p.coefs, 2);
    }

    // ---- fused combine + aggregation outputs ----
    // users: m0*ub_u + m1*ui_u + m2 * (UI_agg @ bi_items)
    k_out<<<ceil_div(NU * 32, TB), TB>>>(rowptr + gs.n_base[3], colval, NU,
                                         (const float4*)bi_acc, NB,
                                         (const float4*)ub_acc, 0, 0.f,
                                         (const float4*)ui_acc, 0,
                                         modal, 0, 1, 2, (float4*)out, 0);
    // bundles: m0*ub_b + m2*bi_b + m1 * (BI_agg @ ui_items)
    k_out<<<ceil_div(NB * 32, TB), TB>>>(rowptr + gs.n_base[4], colval, NB,
                                         (const float4*)ui_acc, NU,
                                         (const float4*)ub_acc, NU, 0.f,
                                         (const float4*)bi_acc, 0,
                                         modal, 0, 2, 1, (float4*)out, NU);
}